// round 5
// baseline (speedup 1.0000x reference)
#include <cuda_runtime.h>
#include <cstdint>

#define KTAGS 16
#define TLEN  512
#define BROWS 1024
#define START_ID 14
#define STOP_ID  15

__device__ float g_row_out[BROWS];
__device__ int   g_ctr = 0;      // last-block counter, self-resetting

// ---- f32x2 packed helpers ----
__device__ __forceinline__ unsigned long long pk2(float lo, float hi) {
    unsigned long long r;
    asm("mov.b64 %0, {%1, %2};" : "=l"(r) : "f"(lo), "f"(hi));
    return r;
}
__device__ __forceinline__ unsigned long long mul2(unsigned long long a, unsigned long long b) {
    unsigned long long r;
    asm("mul.rn.f32x2 %0, %1, %2;" : "=l"(r) : "l"(a), "l"(b));
    return r;
}
__device__ __forceinline__ unsigned long long fma2(unsigned long long a, unsigned long long b,
                                                   unsigned long long c) {
    unsigned long long r;
    asm("fma.rn.f32x2 %0, %1, %2, %3;" : "=l"(r) : "l"(a), "l"(b), "l"(c));
    return r;
}
__device__ __forceinline__ unsigned long long add2(unsigned long long a, unsigned long long b) {
    unsigned long long r;
    asm("add.rn.f32x2 %0, %1, %2;" : "=l"(r) : "l"(a), "l"(b));
    return r;
}
__device__ __forceinline__ float hadd2(unsigned long long a) {
    float lo, hi;
    asm("mov.b64 {%0, %1}, %2;" : "=f"(lo), "=f"(hi) : "l"(a));
    return lo + hi;
}
__device__ __forceinline__ unsigned long long scl2(unsigned long long a, float s) {
    float lo, hi;
    asm("mov.b64 {%0, %1}, %2;" : "=f"(lo), "=f"(hi) : "l"(a));
    return pk2(lo * s, hi * s);
}

// ---------------------------------------------------------------------------
// Fused kernel. 128 threads = 8 groups of 16 lanes; one group per batch row.
// Forward recursion in linear domain with the FULL state vector replicated in
// every lane's registers (8 x f32x2). Per step: local packed dot with the
// lane's Etr row, x own emit, SEL, then 16 width-16 shfl broadcasts. No smem,
// no syncwarp, no redux in the loop.
// ---------------------------------------------------------------------------
__global__ void __launch_bounds__(128)
crf_fused_kernel(const float* __restrict__ h,
                 const int*   __restrict__ y32,      // raw y words (int32 view)
                 const float* __restrict__ mask,
                 const float* __restrict__ trans,
                 float* __restrict__ out) {
    __shared__ float tr_s[256];
    __shared__ int   s_ysh;
    __shared__ int   s_last;
    __shared__ float s_red[4];

    const int tid = threadIdx.x;

    if (tid < 64) ((float4*)tr_s)[tid] = ((const float4*)trans)[tid];

    // y dtype detection: int64 layout -> hi 32-bit word of each u64 is 0.
    if (tid < 32) {
        unsigned long long v = ((const unsigned long long*)y32)[(size_t)tid * 256];
        unsigned bal = __ballot_sync(0xFFFFFFFFu, (unsigned)(v >> 32) != 0u);
        if (tid == 0) s_ysh = (bal == 0u) ? 1 : 0;
    }
    __syncthreads();

    const int lane = tid & 15;
    const int gid  = tid >> 4;                  // 0..7 group in block
    const int row  = blockIdx.x * 8 + gid;
    const unsigned gmask = 0xFFFFu << ((gid & 1) * 16);

    const float* hrow = h    + (size_t)row * TLEN * KTAGS;
    const float* mrow = mask + (size_t)row * TLEN;
    const int ysh = s_ysh;
    const int* yrow = y32 + (((size_t)row * TLEN) << ysh);

    // Etr row of this lane, packed: Etr[i] = exp(trans[lane, i])
    unsigned long long EtrP[8];
#pragma unroll
    for (int k = 0; k < 8; k++)
        EtrP[k] = pk2(__expf(tr_s[lane * 16 + 2 * k]),
                      __expf(tr_s[lane * 16 + 2 * k + 1]));

    // ---- length + gold score (branchless, lane-parallel) ----
    float lsum = 0.f, gsum = 0.f;
#pragma unroll 4
    for (int k = lane; k < TLEN; k += 16) {
        float mk = mrow[k];
        int yt = yrow[k << ysh];
        int yp = (k == 0) ? START_ID : yrow[(k - 1) << ysh];
        lsum += mk;
        gsum = fmaf(mk, hrow[k * 16 + yt] + tr_s[yt * 16 + yp], gsum);
    }
#pragma unroll
    for (int s = 8; s; s >>= 1) {
        lsum += __shfl_xor_sync(gmask, lsum, s, 16);
        gsum += __shfl_xor_sync(gmask, gsum, s, 16);
    }
    const int len = (int)(lsum + 0.5f);
    const int lastTag = yrow[(len - 1) << ysh];
    const float gold = gsum + tr_s[STOP_ID * 16 + lastTag];

    // warp-uniform trip count: max over both groups, rounded up to 8
    int steps = (len + 7) & ~7;
    steps = max(steps, __shfl_xor_sync(0xFFFFFFFFu, steps, 16));

    // ---- forward recursion, invariant alpha_j = C + ln(p_j) ----
    // q = full p vector replicated in every lane; pown = this lane's p_j.
    unsigned long long qp[8];
#pragma unroll
    for (int k = 0; k < 8; k++) qp[k] = 0ull;
    qp[7] = pk2(1.0f, 0.0f);                    // p[14] = 1
    float pown = (lane == START_ID) ? 1.0f : 0.0f;
    float C = 0.0f;

    float hb[8];
#pragma unroll
    for (int d = 0; d < 8; d++) hb[d] = hrow[d * 16 + lane];

    for (int t0 = 0; t0 < steps; t0 += 8) {
        float eh[8];
#pragma unroll
        for (int u = 0; u < 8; u++) eh[u] = __expf(hb[u]);
#pragma unroll
        for (int u = 0; u < 8; u++) {
            int idx = t0 + u + 8;
            idx = (idx > TLEN - 1) ? (TLEN - 1) : idx;
            hb[u] = hrow[idx * 16 + lane];
        }
#pragma unroll
        for (int u = 0; u < 8; u++) {
            const bool act = (t0 + u) < len;
            // S = dot(q, Etr_row) via 4 parallel 2-deep chains
            unsigned long long a0 = fma2(qp[1], EtrP[1], mul2(qp[0], EtrP[0]));
            unsigned long long a1 = fma2(qp[3], EtrP[3], mul2(qp[2], EtrP[2]));
            unsigned long long a2 = fma2(qp[5], EtrP[5], mul2(qp[4], EtrP[4]));
            unsigned long long a3 = fma2(qp[7], EtrP[7], mul2(qp[6], EtrP[6]));
            float S = hadd2(add2(add2(a0, a1), add2(a2, a3)));
            float P = S * eh[u];
            P = act ? P : pown;
            pown = P;
            // broadcast all 16 new values; repack
            float r0  = __shfl_sync(0xFFFFFFFFu, P, 0,  16);
            float r1  = __shfl_sync(0xFFFFFFFFu, P, 1,  16);
            float r2  = __shfl_sync(0xFFFFFFFFu, P, 2,  16);
            float r3  = __shfl_sync(0xFFFFFFFFu, P, 3,  16);
            float r4  = __shfl_sync(0xFFFFFFFFu, P, 4,  16);
            float r5  = __shfl_sync(0xFFFFFFFFu, P, 5,  16);
            float r6  = __shfl_sync(0xFFFFFFFFu, P, 6,  16);
            float r7  = __shfl_sync(0xFFFFFFFFu, P, 7,  16);
            float r8  = __shfl_sync(0xFFFFFFFFu, P, 8,  16);
            float r9  = __shfl_sync(0xFFFFFFFFu, P, 9,  16);
            float r10 = __shfl_sync(0xFFFFFFFFu, P, 10, 16);
            float r11 = __shfl_sync(0xFFFFFFFFu, P, 11, 16);
            float r12 = __shfl_sync(0xFFFFFFFFu, P, 12, 16);
            float r13 = __shfl_sync(0xFFFFFFFFu, P, 13, 16);
            float r14 = __shfl_sync(0xFFFFFFFFu, P, 14, 16);
            float r15 = __shfl_sync(0xFFFFFFFFu, P, 15, 16);
            qp[0] = pk2(r0,  r1);
            qp[1] = pk2(r2,  r3);
            qp[2] = pk2(r4,  r5);
            qp[3] = pk2(r6,  r7);
            qp[4] = pk2(r8,  r9);
            qp[5] = pk2(r10, r11);
            qp[6] = pk2(r12, r13);
            qp[7] = pk2(r14, r15);
        }
        // lane-local exponent renorm (q replicated -> identical in all lanes;
        // exact power of 2; exact no-op for finished rows)
        unsigned mu = 0u;
#pragma unroll
        for (int k = 0; k < 8; k++) {
            float lo, hi;
            asm("mov.b64 {%0, %1}, %2;" : "=f"(lo), "=f"(hi) : "l"(qp[k]));
            mu = max(mu, max(__float_as_uint(lo), __float_as_uint(hi)));
        }
        int me = (int)(mu >> 23);
        me = (me < 1) ? 1 : me;
        float scale = __uint_as_float((unsigned)(254 - me) << 23);  // 2^(127-me)
        C += (float)(me - 127) * 0.6931471805599453f;
#pragma unroll
        for (int k = 0; k < 8; k++) qp[k] = scl2(qp[k], scale);
        pown *= scale;
    }

    // fwd = C + ln( sum_i q_i * exp(trans[STOP, i]) ) — lane-local (q replicated)
    unsigned long long acc = 0ull;
#pragma unroll
    for (int k = 0; k < 8; k++) {
        unsigned long long es = pk2(__expf(tr_s[STOP_ID * 16 + 2 * k]),
                                    __expf(tr_s[STOP_ID * 16 + 2 * k + 1]));
        acc = fma2(qp[k], es, acc);
    }
    const float fwd = C + __logf(hadd2(acc));

    if (lane == 0) g_row_out[row] = fwd - gold;

    // ---- last-block mean reduction ----
    __threadfence();
    __syncthreads();
    if (tid == 0) {
        int old = atomicAdd(&g_ctr, 1);
        s_last = (old == gridDim.x - 1);
    }
    __syncthreads();
    if (s_last) {
        float s = 0.f;
#pragma unroll
        for (int i = 0; i < BROWS / 128; i++)
            s += g_row_out[tid + i * 128];
#pragma unroll
        for (int sft = 16; sft; sft >>= 1)
            s += __shfl_xor_sync(0xFFFFFFFFu, s, sft);
        if ((tid & 31) == 0) s_red[tid >> 5] = s;
        __syncthreads();
        if (tid == 0) {
            float tot = s_red[0] + s_red[1] + s_red[2] + s_red[3];
            out[0] = tot * (1.0f / (float)BROWS);
            g_ctr = 0;   // reset for next graph replay
        }
    }
}

// ---------------------------------------------------------------------------
extern "C" void kernel_launch(void* const* d_in, const int* in_sizes, int n_in,
                              void* d_out, int out_size) {
    const float* h     = (const float*)d_in[0];
    const int*   y     = (const int*)d_in[1];
    const float* mask  = (const float*)d_in[2];
    const float* trans = (const float*)d_in[3];
    float* out = (float*)d_out;

    crf_fused_kernel<<<BROWS / 8, 128>>>(h, y, mask, trans, out);
}

// round 6
// speedup vs baseline: 1.2543x; 1.2543x over previous
#include <cuda_runtime.h>
#include <cstdint>

#define KTAGS 16
#define TLEN  512
#define BROWS 1024
#define START_ID 14
#define STOP_ID  15

__device__ float g_row_out[BROWS];
__device__ int   g_ctr = 0;      // last-block counter, self-resetting

typedef unsigned long long u64;

// ---- f32x2 packed helpers ----
__device__ __forceinline__ u64 pk2(float lo, float hi) {
    u64 r; asm("mov.b64 %0, {%1, %2};" : "=l"(r) : "f"(lo), "f"(hi)); return r;
}
__device__ __forceinline__ u64 mul2(u64 a, u64 b) {
    u64 r; asm("mul.rn.f32x2 %0, %1, %2;" : "=l"(r) : "l"(a), "l"(b)); return r;
}
__device__ __forceinline__ u64 fma2(u64 a, u64 b, u64 c) {
    u64 r; asm("fma.rn.f32x2 %0, %1, %2, %3;" : "=l"(r) : "l"(a), "l"(b), "l"(c)); return r;
}
__device__ __forceinline__ u64 add2(u64 a, u64 b) {
    u64 r; asm("add.rn.f32x2 %0, %1, %2;" : "=l"(r) : "l"(a), "l"(b)); return r;
}
__device__ __forceinline__ float hadd2(u64 a) {
    float lo, hi;
    asm("mov.b64 {%0, %1}, %2;" : "=f"(lo), "=f"(hi) : "l"(a));
    return lo + hi;
}

// ---------------------------------------------------------------------------
// Fused kernel. 128 threads = 8 groups of 16 lanes; one group per batch row.
// Forward recursion in linear domain: alpha_j = C + ln(p_j).
// Exchange via double-buffered smem (STS.32 + syncwarp + 4x LDS.128 read as
// ulonglong2 -> direct f32x2 operands). Exponent-only renorm every 8 steps
// computed lane-locally from the already-loaded q registers (stale-by-1 max;
// exact for any power-of-2 scale).
// ---------------------------------------------------------------------------
__global__ void __launch_bounds__(128)
crf_fused_kernel(const float* __restrict__ h,
                 const int*   __restrict__ y32,      // raw y words (int32 view)
                 const float* __restrict__ mask,
                 const float* __restrict__ trans,
                 float* __restrict__ out) {
    __shared__ float tr_s[256];
    __shared__ __align__(16) float pbuf[2][8][16];   // [parity][group][state]
    __shared__ int   s_ysh;
    __shared__ int   s_last;
    __shared__ float s_red[4];

    const int tid = threadIdx.x;

    if (tid < 64) ((float4*)tr_s)[tid] = ((const float4*)trans)[tid];

    // y dtype detection: int64 layout -> hi 32-bit word of each u64 is 0.
    if (tid < 32) {
        u64 v = ((const u64*)y32)[(size_t)tid * 256];
        unsigned bal = __ballot_sync(0xFFFFFFFFu, (unsigned)(v >> 32) != 0u);
        if (tid == 0) s_ysh = (bal == 0u) ? 1 : 0;
    }
    __syncthreads();

    const int lane = tid & 15;
    const int gid  = tid >> 4;                  // 0..7 group in block
    const int row  = blockIdx.x * 8 + gid;
    const unsigned gmask = 0xFFFFu << ((gid & 1) * 16);

    const float* hrow = h    + (size_t)row * TLEN * KTAGS;
    const float* mrow = mask + (size_t)row * TLEN;
    const int ysh = s_ysh;
    const int* yrow = y32 + (((size_t)row * TLEN) << ysh);

    // Etr row of this lane, packed: Etr[i] = exp(trans[lane, i]).
    u64 EtrP[8];
#pragma unroll
    for (int k = 0; k < 8; k++)
        EtrP[k] = pk2(__expf(tr_s[lane * 16 + 2 * k]),
                      __expf(tr_s[lane * 16 + 2 * k + 1]));
    const float EtrStop = __expf(tr_s[STOP_ID * 16 + lane]);

    // ---- length + gold score (branchless, lane-parallel) ----
    float lsum = 0.f, gsum = 0.f;
#pragma unroll 4
    for (int k = lane; k < TLEN; k += 16) {
        float mk = mrow[k];
        int yt = yrow[k << ysh];
        int yp = (k == 0) ? START_ID : yrow[(k - 1) << ysh];
        lsum += mk;
        gsum = fmaf(mk, hrow[k * 16 + yt] + tr_s[yt * 16 + yp], gsum);
    }
#pragma unroll
    for (int s = 8; s; s >>= 1) {
        lsum += __shfl_xor_sync(gmask, lsum, s, 16);
        gsum += __shfl_xor_sync(gmask, gsum, s, 16);
    }
    const int len = (int)(lsum + 0.5f);
    const int lastTag = yrow[(len - 1) << ysh];
    const float gold = gsum + tr_s[STOP_ID * 16 + lastTag];

    // warp-uniform trip count: max over both groups, rounded up to 8
    int steps = (len + 7) & ~7;
    steps = max(steps, __shfl_xor_sync(0xFFFFFFFFu, steps, 16));

    // ---- forward recursion ----
    float p = (lane == START_ID) ? 1.0f : 0.0f;
    float C = 0.0f;

    float hb[8];
#pragma unroll
    for (int d = 0; d < 8; d++) hb[d] = hrow[d * 16 + lane];

    for (int t0 = 0; t0 < steps; t0 += 8) {
        float eh[8];
#pragma unroll
        for (int u = 0; u < 8; u++) eh[u] = __expf(hb[u]);
#pragma unroll
        for (int u = 0; u < 8; u++) {
            int idx = t0 + u + 8;
            idx = (idx > TLEN - 1) ? (TLEN - 1) : idx;
            hb[u] = hrow[idx * 16 + lane];
        }

        unsigned mu = 0u;       // lane-local max of q bits at u==7 (stale-by-1)

#pragma unroll
        for (int u = 0; u < 8; u++) {
            const bool act = (t0 + u) < len;      // group-uniform -> FSEL
            float* buf = pbuf[u & 1][gid];
            buf[lane] = p;
            __syncwarp();
            const ulonglong2* bp = (const ulonglong2*)buf;
            const ulonglong2 v0 = bp[0];
            const ulonglong2 v1 = bp[1];

            u64 a0 = fma2(v0.y, EtrP[1], mul2(v0.x, EtrP[0]));
            u64 a1 = fma2(v1.y, EtrP[3], mul2(v1.x, EtrP[2]));
            const ulonglong2 v2 = bp[2];
            const ulonglong2 v3 = bp[3];
            u64 a2 = fma2(v2.y, EtrP[5], mul2(v2.x, EtrP[4]));
            u64 a3 = fma2(v3.y, EtrP[7], mul2(v3.x, EtrP[6]));

            float S = hadd2(add2(add2(a0, a1), add2(a2, a3)));
            float pn = S * eh[u];
            p = act ? pn : p;

            if (u == 7) {
                // off-chain: max over the 16 q floats (non-negative => uint max)
                unsigned m0 = max((unsigned)v0.x, (unsigned)(v0.x >> 32));
                unsigned m1 = max((unsigned)v0.y, (unsigned)(v0.y >> 32));
                unsigned m2 = max((unsigned)v1.x, (unsigned)(v1.x >> 32));
                unsigned m3 = max((unsigned)v1.y, (unsigned)(v1.y >> 32));
                unsigned m4 = max((unsigned)v2.x, (unsigned)(v2.x >> 32));
                unsigned m5 = max((unsigned)v2.y, (unsigned)(v2.y >> 32));
                unsigned m6 = max((unsigned)v3.x, (unsigned)(v3.x >> 32));
                unsigned m7 = max((unsigned)v3.y, (unsigned)(v3.y >> 32));
                mu = max(max(max(m0, m1), max(m2, m3)),
                         max(max(m4, m5), max(m6, m7)));
            }
        }
        // exponent-only renorm: exact for any power-of-2 scale (invariant
        // alpha = C + ln p preserved, incl. frozen rows)
        int me = (int)(mu >> 23);
        me = (me < 1) ? 1 : me;
        float scale = __uint_as_float((unsigned)(254 - me) << 23);  // 2^(127-me)
        C += (float)(me - 127) * 0.6931471805599453f;
        p *= scale;
    }

    // fwd = C + ln( sum_j p_j * exp(trans[STOP, j]) )
    float v = p * EtrStop;
#pragma unroll
    for (int s = 8; s; s >>= 1)
        v += __shfl_xor_sync(gmask, v, s, 16);
    const float fwd = C + __logf(v);

    if (lane == 0) g_row_out[row] = fwd - gold;

    // ---- last-block mean reduction ----
    __threadfence();
    __syncthreads();
    if (tid == 0) {
        int old = atomicAdd(&g_ctr, 1);
        s_last = (old == gridDim.x - 1);
    }
    __syncthreads();
    if (s_last) {
        float s = 0.f;
#pragma unroll
        for (int i = 0; i < BROWS / 128; i++)
            s += g_row_out[tid + i * 128];
#pragma unroll
        for (int sft = 16; sft; sft >>= 1)
            s += __shfl_xor_sync(0xFFFFFFFFu, s, sft);
        if ((tid & 31) == 0) s_red[tid >> 5] = s;
        __syncthreads();
        if (tid == 0) {
            float tot = s_red[0] + s_red[1] + s_red[2] + s_red[3];
            out[0] = tot * (1.0f / (float)BROWS);
            g_ctr = 0;   // reset for next graph replay
        }
    }
}

// ---------------------------------------------------------------------------
extern "C" void kernel_launch(void* const* d_in, const int* in_sizes, int n_in,
                              void* d_out, int out_size) {
    const float* h     = (const float*)d_in[0];
    const int*   y     = (const int*)d_in[1];
    const float* mask  = (const float*)d_in[2];
    const float* trans = (const float*)d_in[3];
    float* out = (float*)d_out;

    crf_fused_kernel<<<BROWS / 8, 128>>>(h, y, mask, trans, out);
}